// round 15
// baseline (speedup 1.0000x reference)
#include <cuda_runtime.h>
#include <cuda_fp16.h>
#include <math.h>
#include <stdint.h>

// ---------------------------------------------------------------------------
// Decomposable-Attention NLI forward. mma.sync fp16 hi/lo-split (3 products).
// 128x64 block tile, 256 threads (8 warps 4x2, 32x32 warp tile), 2 CTAs/SM.
// K32 stages with hi|lo interleaved in 128B rows -> 24KB stage, 4-stage ring,
// single __syncthreads per stage, refill 3 ahead. B=32, L=256, D=1024, FF=2048.
// ---------------------------------------------------------------------------

// fp16 scratch offsets (elements)
#define O_PH_H 0L
#define O_PH_L 8388608L
#define O_HH_H 16777216L
#define O_HH_L 25165824L
#define O_FP_H 33554432L
#define O_FP_L 41943040L
#define O_FH_H 50331648L
#define O_FH_L 58720256L
#define O_PT_H 67108864L
#define O_PT_L 75497472L
#define O_HT_H 83886080L
#define O_HT_L 92274688L
#define O_BE_H 100663296L
#define O_BE_L 109051904L
#define O_AL_H 117440512L
#define O_AL_L 125829120L
#define O_WF_H 134217728L
#define O_WF_L 135266304L
#define O_WG_H 136314880L
#define O_WG_L 140509184L
#define O_AT_H 144703488L
#define O_AT_L 146800640L
#define O_TT_H 148897792L
#define O_TT_L 150994944L
#define BF_TOTAL 153092096L
#define OF_E  0L
#define OF_S1 2097152L
#define OF_S2 2162688L
#define OF_A1 2228224L
#define OF_A2 2293760L
#define F32_TOTAL 2359296L

__half __device__ __align__(1024) g_hf[BF_TOTAL];
float __device__ __align__(1024) g_f32[F32_TOTAL];

// stage layout (bytes): A (128 rows x 128B, hi|lo interleaved) 16K | B (64 rows) 8K
#define ST_B  16384
#define ST_SZ 24576

__device__ __forceinline__ uint32_t smem_u32(const void* p) {
    uint32_t a;
    asm("{ .reg .u64 t; cvta.to.shared.u64 t, %1; cvt.u32.u64 %0, t; }" : "=r"(a) : "l"(p));
    return a;
}
__device__ __forceinline__ void split1(float v, __half& h, __half& l) {
    h = __float2half_rn(v);
    l = __float2half_rn(v - __half2float(h));
}
__device__ __forceinline__ uint32_t pk(__half a, __half b) {
    return (uint32_t)__half_as_ushort(a) | ((uint32_t)__half_as_ushort(b) << 16);
}
__device__ __forceinline__ void mma_f16(float* c, const uint32_t* a, const uint32_t* b) {
    asm volatile(
        "mma.sync.aligned.m16n8k16.row.col.f32.f16.f16.f32 "
        "{%0,%1,%2,%3},{%4,%5,%6,%7},{%8,%9},{%0,%1,%2,%3};\n"
        : "+f"(c[0]), "+f"(c[1]), "+f"(c[2]), "+f"(c[3])
        : "r"(a[0]), "r"(a[1]), "r"(a[2]), "r"(a[3]), "r"(b[0]), "r"(b[1]));
}
__device__ __forceinline__ void ldsm4(uint32_t* r, uint32_t addr) {
    asm volatile("ldmatrix.sync.aligned.m8n8.x4.shared.b16 {%0,%1,%2,%3}, [%4];"
                 : "=r"(r[0]), "=r"(r[1]), "=r"(r[2]), "=r"(r[3]) : "r"(addr));
}

// cp.async a ROWS x K32 hi|lo-interleaved tile (128B rows, SW128); 256 threads.
// chunks c<4 from gh (k = c*8..), c>=4 from gl (k = (c-4)*8..).
template <int ROWS>
__device__ __forceinline__ void ld_int(uint32_t sb, const __half* gh, const __half* gl,
                                       long ld, int t) {
    constexpr int ITERS = ROWS * 8 / 256;
#pragma unroll
    for (int i = 0; i < ITERS; i++) {
        const int idx = t + i * 256;
        const int r = idx >> 3, c = idx & 7;
        const __half* src = (c < 4) ? gh + (long)r * ld + c * 8
                                    : gl + (long)r * ld + (c - 4) * 8;
        uint32_t dst = sb + r * 128 + ((c ^ (r & 7)) << 4);
        asm volatile("cp.async.cg.shared.global [%0], [%1], 16;"
                     :: "r"(dst), "l"(src) : "memory");
    }
}

// Precompute stage-relative ldmatrix offsets (hi: chunks 0..3, lo: chunks 4..7).
__device__ __forceinline__ void mk_addrs(uint32_t aAh[2][2], uint32_t aAl[2][2],
                                         uint32_t aBh[2][2], uint32_t aBl[2][2],
                                         int wm, int wn, int lane) {
    const int lm = lane & 7, mat = lane >> 3;
    const int rsel = (mat & 1) * 8 + lm;
    const int csel = mat >> 1;
#pragma unroll
    for (int s = 0; s < 2; s++) {
        const int ch = 2 * s + csel;
#pragma unroll
        for (int mf = 0; mf < 2; mf++) {
            const int rm = wm * 32 + mf * 16 + rsel;
            aAh[mf][s] = rm * 128 + ((ch ^ (rm & 7)) << 4);
            aAl[mf][s] = rm * 128 + (((ch + 4) ^ (rm & 7)) << 4);
        }
#pragma unroll
        for (int nfp = 0; nfp < 2; nfp++) {
            const int rn = wn * 32 + nfp * 16 + rsel;
            aBh[nfp][s] = rn * 128 + ((ch ^ (rn & 7)) << 4);
            aBl[nfp][s] = rn * 128 + (((ch + 4) ^ (rn & 7)) << 4);
        }
    }
}

// warp compute over one K32 stage, product-major (8 independent mma per pass).
__device__ __forceinline__ void wcompute(uint32_t sb, const uint32_t aAh[2][2],
                                         const uint32_t aAl[2][2], const uint32_t aBh[2][2],
                                         const uint32_t aBl[2][2], float acc[2][4][4]) {
#pragma unroll
    for (int s = 0; s < 2; s++) {
        uint32_t bh[4][2], bl[4][2];
#pragma unroll
        for (int nfp = 0; nfp < 2; nfp++) {
            uint32_t q[4];
            ldsm4(q, sb + ST_B + aBh[nfp][s]);
            bh[nfp * 2][0] = q[0]; bh[nfp * 2 + 1][0] = q[1];
            bh[nfp * 2][1] = q[2]; bh[nfp * 2 + 1][1] = q[3];
            ldsm4(q, sb + ST_B + aBl[nfp][s]);
            bl[nfp * 2][0] = q[0]; bl[nfp * 2 + 1][0] = q[1];
            bl[nfp * 2][1] = q[2]; bl[nfp * 2 + 1][1] = q[3];
        }
        uint32_t ah[2][4], al[2][4];
#pragma unroll
        for (int mf = 0; mf < 2; mf++) {
            ldsm4(ah[mf], sb + aAh[mf][s]);
            ldsm4(al[mf], sb + aAl[mf][s]);
        }
#pragma unroll
        for (int mf = 0; mf < 2; mf++)
#pragma unroll
            for (int nf = 0; nf < 4; nf++) mma_f16(acc[mf][nf], ah[mf], bh[nf]);
#pragma unroll
        for (int mf = 0; mf < 2; mf++)
#pragma unroll
            for (int nf = 0; nf < 4; nf++) mma_f16(acc[mf][nf], ah[mf], bl[nf]);
#pragma unroll
        for (int mf = 0; mf < 2; mf++)
#pragma unroll
            for (int nf = 0; nf < 4; nf++) mma_f16(acc[mf][nf], al[mf], bh[nf]);
    }
}

#define CP_WAIT_FOR(rem) do {                                               \
    if ((rem) >= 2)      asm volatile("cp.async.wait_group 2;" ::: "memory"); \
    else if ((rem) == 1) asm volatile("cp.async.wait_group 1;" ::: "memory"); \
    else                 asm volatile("cp.async.wait_group 0;" ::: "memory"); \
} while (0)

// ---------------------------------------------------------------------------
// D = A @ B^T. A[m][k], B[n][k] fp16 h/l row-major. Block tile 128x64,
// 256 threads, 4-stage K32 ring, single sync per stage, 2 CTAs/SM.
// EPI: 0 = fp32 store; 1 = hi/lo pack store; 2 = tanh + pack store.
// ---------------------------------------------------------------------------
template <int EPI>
__global__ __launch_bounds__(256, 2) void mm(
    const __half* __restrict__ Ah, const __half* __restrict__ Al, long lda, long sA,
    const __half* __restrict__ Bh, const __half* __restrict__ Bl, long ldb, long sB,
    float* __restrict__ Cf, long ldc, long sC,
    __half* __restrict__ Oh, __half* __restrict__ Ol, long ldo, long sO, int K)
{
    extern __shared__ __align__(16) char dsm[];
    const uint32_t base = smem_u32(dsm);
    const int t = threadIdx.x, lane = t & 31, wid = t >> 5;
    const int wm = wid >> 1, wn = wid & 1;
    const int bm = blockIdx.y * 128, bn = blockIdx.x * 64, z = blockIdx.z;

    const __half* Azh = Ah + z * sA + (long)bm * lda;
    const __half* Azl = Al + z * sA + (long)bm * lda;
    const __half* Bzh = Bh + z * sB + (long)bn * ldb;
    const __half* Bzl = Bl + z * sB + (long)bn * ldb;
    const int ns = K >> 5;

    uint32_t aAh[2][2], aAl[2][2], aBh[2][2], aBl[2][2];
    mk_addrs(aAh, aAl, aBh, aBl, wm, wn, lane);

    float acc[2][4][4];
#pragma unroll
    for (int i = 0; i < 2; i++)
#pragma unroll
        for (int j = 0; j < 4; j++)
#pragma unroll
            for (int q = 0; q < 4; q++) acc[i][j][q] = 0.f;

    auto issue = [&](int j) {
        const uint32_t sb = base + (j & 3) * ST_SZ;
        const long ko = (long)j << 5;
        ld_int<128>(sb,        Azh + ko, Azl + ko, lda, t);
        ld_int<64>(sb + ST_B,  Bzh + ko, Bzl + ko, ldb, t);
        asm volatile("cp.async.commit_group;" ::: "memory");
    };

    issue(0); issue(1); issue(2);
    for (int j = 0; j < ns; j++) {
        CP_WAIT_FOR(ns - 1 - j);
        __syncthreads();
        if (j + 3 < ns) issue(j + 3);
        wcompute(base + (j & 3) * ST_SZ, aAh, aAl, aBh, aBl, acc);
    }

    const int r = lane >> 2, c2 = (lane & 3) * 2;
#pragma unroll
    for (int mf = 0; mf < 2; mf++)
#pragma unroll
        for (int nf = 0; nf < 4; nf++) {
            const int row = bm + wm * 32 + mf * 16 + r;
            const int col = bn + wn * 32 + nf * 8 + c2;
            float v0 = acc[mf][nf][0], v1 = acc[mf][nf][1];
            float v2 = acc[mf][nf][2], v3 = acc[mf][nf][3];
            if (EPI == 2) { v0 = tanhf(v0); v1 = tanhf(v1); v2 = tanhf(v2); v3 = tanhf(v3); }
            if (EPI == 0) {
                *(float2*)&Cf[z * sC + (long)row * ldc + col] = make_float2(v0, v1);
                *(float2*)&Cf[z * sC + (long)(row + 8) * ldc + col] = make_float2(v2, v3);
            } else {
                __half h0, l0, h1, l1;
                split1(v0, h0, l0); split1(v1, h1, l1);
                const long o0 = z * sO + (long)row * ldo + col;
                *(uint32_t*)&Oh[o0] = pk(h0, h1);
                *(uint32_t*)&Ol[o0] = pk(l0, l1);
                split1(v2, h0, l0); split1(v3, h1, l1);
                const long o1 = z * sO + (long)(row + 8) * ldo + col;
                *(uint32_t*)&Oh[o1] = pk(h0, h1);
                *(uint32_t*)&Ol[o1] = pk(l0, l1);
            }
        }
}

// ---------------------------------------------------------------------------
// Fused compare (S1+S2 in one launch, z in [0,64)):
// half = z>>5 selects (X1,X2,S); S[zz,n] = sum_p tanh(concat(X1,X2)[zz,p,:] @ W[:,n])
// ---------------------------------------------------------------------------
__global__ __launch_bounds__(256, 2) void mm_compare(
    const __half* __restrict__ P1h, const __half* __restrict__ P1l,
    const __half* __restrict__ P2h, const __half* __restrict__ P2l,
    const __half* __restrict__ Q1h, const __half* __restrict__ Q1l,
    const __half* __restrict__ Q2h, const __half* __restrict__ Q2l,
    const __half* __restrict__ Wh,  const __half* __restrict__ Wl,
    float* __restrict__ S1, float* __restrict__ S2)
{
    extern __shared__ __align__(16) char dsm[];
    __shared__ float red[4][64];
    const uint32_t base = smem_u32(dsm);
    const int t = threadIdx.x, lane = t & 31, wid = t >> 5;
    const int wm = wid >> 1, wn = wid & 1;
    const int bn = blockIdx.x * 64;
    const int half = blockIdx.z >> 5, z = blockIdx.z & 31;

    const __half* X1h = half ? P2h : P1h;
    const __half* X1l = half ? P2l : P1l;
    const __half* X2h = half ? Q2h : Q1h;
    const __half* X2l = half ? Q2l : Q1l;
    float* S = half ? S2 : S1;

    const __half* Wbh = Wh + (long)bn * 2048;
    const __half* Wbl = Wl + (long)bn * 2048;

    uint32_t aAh[2][2], aAl[2][2], aBh[2][2], aBl[2][2];
    mk_addrs(aAh, aAl, aBh, aBl, wm, wn, lane);

    float csum[4][2];
#pragma unroll
    for (int nf = 0; nf < 4; nf++) { csum[nf][0] = 0.f; csum[nf][1] = 0.f; }

    for (int mt = 0; mt < 2; mt++) {
        float acc[2][4][4];
#pragma unroll
        for (int i = 0; i < 2; i++)
#pragma unroll
            for (int j = 0; j < 4; j++)
#pragma unroll
                for (int q = 0; q < 4; q++) acc[i][j][q] = 0.f;

        auto issue = [&](int j) {
            const uint32_t sb = base + (j & 3) * ST_SZ;
            const long ro = (long)z * 262144 + (long)mt * 131072;
            const long ko = (long)(j & 31) << 5;
            const __half* axh = (j < 32) ? X1h + ro + ko : X2h + ro + ko;
            const __half* axl = (j < 32) ? X1l + ro + ko : X2l + ro + ko;
            ld_int<128>(sb,       axh, axl, 1024, t);
            ld_int<64>(sb + ST_B, Wbh + ((long)j << 5), Wbl + ((long)j << 5), 2048, t);
            asm volatile("cp.async.commit_group;" ::: "memory");
        };

        issue(0); issue(1); issue(2);
        for (int j = 0; j < 64; j++) {
            CP_WAIT_FOR(63 - j);
            __syncthreads();
            if (j + 3 < 64) issue(j + 3);
            wcompute(base + (j & 3) * ST_SZ, aAh, aAl, aBh, aBl, acc);
        }
#pragma unroll
        for (int mf = 0; mf < 2; mf++)
#pragma unroll
            for (int nf = 0; nf < 4; nf++) {
                csum[nf][0] += tanhf(acc[mf][nf][0]) + tanhf(acc[mf][nf][2]);
                csum[nf][1] += tanhf(acc[mf][nf][1]) + tanhf(acc[mf][nf][3]);
            }
    }

    // reduce the 8 row-groups within the warp (lanes sharing lane&3)
#pragma unroll
    for (int off = 4; off <= 16; off <<= 1)
#pragma unroll
        for (int nf = 0; nf < 4; nf++) {
            csum[nf][0] += __shfl_xor_sync(0xffffffffu, csum[nf][0], off);
            csum[nf][1] += __shfl_xor_sync(0xffffffffu, csum[nf][1], off);
        }
    __syncthreads();  // all warps done with wcompute(63) before red reuse timing
    if (lane < 4) {
#pragma unroll
        for (int nf = 0; nf < 4; nf++) {
            red[wm][wn * 32 + nf * 8 + 2 * lane + 0] = csum[nf][0];
            red[wm][wn * 32 + nf * 8 + 2 * lane + 1] = csum[nf][1];
        }
    }
    __syncthreads();
    if (t < 64)
        S[(long)z * 2048 + bn + t] = red[0][t] + red[1][t] + red[2][t] + red[3][t];
}

// fp32 row-major -> elementwise fp16 hi/lo (same layout); two tensors via grid.y
__global__ __launch_bounds__(256) void pack_nat2(
    const float* __restrict__ X0, const float* __restrict__ X1,
    __half* __restrict__ H0, __half* __restrict__ L0,
    __half* __restrict__ H1, __half* __restrict__ L1, long n4)
{
    const long i = (long)blockIdx.x * 256 + threadIdx.x;
    if (i >= n4) return;
    const float* X = blockIdx.y ? X1 : X0;
    __half* H = blockIdx.y ? H1 : H0;
    __half* L = blockIdx.y ? L1 : L0;
    float4 v = ((const float4*)X)[i];
    __half h[4], l[4];
    split1(v.x, h[0], l[0]); split1(v.y, h[1], l[1]);
    split1(v.z, h[2], l[2]); split1(v.w, h[3], l[3]);
    ((uint2*)H)[i] = make_uint2(pk(h[0], h[1]), pk(h[2], h[3]));
    ((uint2*)L)[i] = make_uint2(pk(l[0], l[1]), pk(l[2], l[3]));
}

// fp32 [Z][R][C] -> fp16 hi/lo [Z][C][R]
__global__ __launch_bounds__(256) void pack_T(
    const float* __restrict__ X, __half* __restrict__ H,
    __half* __restrict__ L, int R, int C)
{
    __shared__ float tile[32][33];
    const int c0 = blockIdx.x * 32, r0 = blockIdx.y * 32;
    const int tx = threadIdx.x & 31, ty = threadIdx.x >> 5;
    const long zoff = (long)blockIdx.z * R * C;
#pragma unroll
    for (int i = 0; i < 4; i++)
        tile[ty + i * 8][tx] = X[zoff + (long)(r0 + ty + i * 8) * C + c0 + tx];
    __syncthreads();
#pragma unroll
    for (int i = 0; i < 4; i++) {
        const int c = ty + i * 8;
        __half h, l;
        split1(tile[tx][c], h, l);
        H[zoff + (long)(c0 + c) * R + r0 + tx] = h;
        L[zoff + (long)(c0 + c) * R + r0 + tx] = l;
    }
}

// softmax over 256 cols; writes attn [b][p][h] and attn^T [b][h][p] hi/lo
__global__ void softmax_pack(
    const float* __restrict__ E,
    __half* __restrict__ ATh, __half* __restrict__ ATl,
    __half* __restrict__ TTh, __half* __restrict__ TTl)
{
    __shared__ float sm[8][257];
    const int b = blockIdx.x >> 5;
    const int p0 = (blockIdx.x & 31) << 3;
    const int lane = threadIdx.x, ty = threadIdx.y;
    const float* row = E + ((long)b * 256 + p0 + ty) * 256;
    float v[8];
    float mx = -1e30f;
#pragma unroll
    for (int i = 0; i < 8; i++) { v[i] = row[i * 32 + lane]; mx = fmaxf(mx, v[i]); }
#pragma unroll
    for (int o = 16; o; o >>= 1) mx = fmaxf(mx, __shfl_xor_sync(0xffffffffu, mx, o));
    float s = 0.f;
#pragma unroll
    for (int i = 0; i < 8; i++) { v[i] = expf(v[i] - mx); s += v[i]; }
#pragma unroll
    for (int o = 16; o; o >>= 1) s += __shfl_xor_sync(0xffffffffu, s, o);
    const float inv = 1.0f / s;
#pragma unroll
    for (int i = 0; i < 8; i++) sm[ty][i * 32 + lane] = v[i] * inv;
    __syncthreads();
    const int t = ty * 32 + lane;
    {
        const int pr = t >> 5, c0 = (t & 31) << 3;
        uint32_t hw[4], lw[4];
#pragma unroll
        for (int q = 0; q < 4; q++) {
            __half h0, l0, h1, l1;
            split1(sm[pr][c0 + 2 * q], h0, l0); split1(sm[pr][c0 + 2 * q + 1], h1, l1);
            hw[q] = pk(h0, h1); lw[q] = pk(l0, l1);
        }
        const long o = ((long)b * 256 + p0 + pr) * 256 + c0;
        *(uint4*)&ATh[o] = make_uint4(hw[0], hw[1], hw[2], hw[3]);
        *(uint4*)&ATl[o] = make_uint4(lw[0], lw[1], lw[2], lw[3]);
    }
    {
        uint32_t hw[4], lw[4];
#pragma unroll
        for (int q = 0; q < 4; q++) {
            __half h0, l0, h1, l1;
            split1(sm[2 * q][t], h0, l0); split1(sm[2 * q + 1][t], h1, l1);
            hw[q] = pk(h0, h1); lw[q] = pk(l0, l1);
        }
        const long o = ((long)b * 256 + t) * 256 + p0;
        *(uint4*)&TTh[o] = make_uint4(hw[0], hw[1], hw[2], hw[3]);
        *(uint4*)&TTl[o] = make_uint4(lw[0], lw[1], lw[2], lw[3]);
    }
}

__global__ __launch_bounds__(128) void mlp_layer_kernel(
    const float* __restrict__ A1, const float* __restrict__ A2, int ksplit,
    const float* __restrict__ W, const float* __restrict__ bias,
    float* __restrict__ out, int N, int K, int do_tanh)
{
    const int n = blockIdx.x * 128 + threadIdx.x;
    const int m0 = blockIdx.y * 8;
    __shared__ float As[8][129];
    float acc[8];
#pragma unroll
    for (int i = 0; i < 8; i++) acc[i] = 0.f;
    for (int k0 = 0; k0 < K; k0 += 128) {
#pragma unroll
        for (int i = 0; i < 8; i++) {
            const int k = k0 + threadIdx.x;
            As[i][threadIdx.x] = (k < ksplit)
                ? A1[(long)(m0 + i) * ksplit + k]
                : A2[(long)(m0 + i) * ksplit + (k - ksplit)];
        }
        __syncthreads();
        for (int kk = 0; kk < 128; kk++) {
            const float wv = W[(long)(k0 + kk) * N + n];
#pragma unroll
            for (int i = 0; i < 8; i++) acc[i] += As[i][kk] * wv;
        }
        __syncthreads();
    }
    const float bb = bias[n];
#pragma unroll
    for (int i = 0; i < 8; i++) {
        float r = acc[i] + bb;
        out[(long)(m0 + i) * N + n] = do_tanh ? tanhf(r) : r;
    }
}

__global__ void final_layer_kernel(
    const float* __restrict__ A, const float* __restrict__ W3,
    const float* __restrict__ b3, float* __restrict__ out)
{
    const int m = blockIdx.x / 3, n = blockIdx.x % 3, lane = threadIdx.x;
    float s = 0.f;
    for (int k = lane; k < 2048; k += 32)
        s += A[(long)m * 2048 + k] * W3[(long)k * 3 + n];
#pragma unroll
    for (int o = 16; o; o >>= 1) s += __shfl_xor_sync(0xffffffffu, s, o);
    if (lane == 0) out[m * 3 + n] = s + b3[n];
}

extern "C" void kernel_launch(void* const* d_in, const int* in_sizes, int n_in,
                              void* d_out, int out_size)
{
    const float* P   = (const float*)d_in[0];
    const float* Hy  = (const float*)d_in[1];
    const float* W_F = (const float*)d_in[2];
    const float* W_G = (const float*)d_in[3];
    const float* W1  = (const float*)d_in[4];
    const float* b1  = (const float*)d_in[5];
    const float* W2  = (const float*)d_in[6];
    const float* b2  = (const float*)d_in[7];
    const float* W3  = (const float*)d_in[8];
    const float* b3  = (const float*)d_in[9];
    float* out = (float*)d_out;

    __half* hf = nullptr;
    float* f32 = nullptr;
    cudaGetSymbolAddress((void**)&hf, g_hf);
    cudaGetSymbolAddress((void**)&f32, g_f32);

    const int SM = 4 * ST_SZ;  // 96KB dynamic -> 2 CTAs/SM
    cudaFuncSetAttribute(mm<0>, cudaFuncAttributeMaxDynamicSharedMemorySize, SM);
    cudaFuncSetAttribute(mm<1>, cudaFuncAttributeMaxDynamicSharedMemorySize, SM);
    cudaFuncSetAttribute(mm<2>, cudaFuncAttributeMaxDynamicSharedMemorySize, SM);
    cudaFuncSetAttribute(mm_compare, cudaFuncAttributeMaxDynamicSharedMemorySize, SM);

    float* E  = f32 + OF_E;
    float* S1 = f32 + OF_S1;
    float* S2 = f32 + OF_S2;
    float* a1 = f32 + OF_A1;
    float* a2 = f32 + OF_A2;

    pack_nat2<<<dim3(8192, 2), 256>>>(P, Hy, hf + O_PH_H, hf + O_PH_L,
                                      hf + O_HH_H, hf + O_HH_L, 2097152);        // 0
    pack_T<<<dim3(32, 32, 1), 256>>>(W_F, hf + O_WF_H, hf + O_WF_L, 1024, 1024); // 1
    pack_T<<<dim3(64, 64, 1), 256>>>(W_G, hf + O_WG_H, hf + O_WG_L, 2048, 2048); // 2

    // fused projections: z=0 -> P, z=1 -> H (batch stride = PH->HH offset)
    mm<2><<<dim3(16, 64, 2), 256, SM>>>(                                         // 3 <- ncu
        hf + O_PH_H, hf + O_PH_L, 1024, 16777216,
        hf + O_WF_H, hf + O_WF_L, 1024, 0,
        nullptr, 0, 0, hf + O_FP_H, hf + O_FP_L, 1024, 16777216, 1024);

    pack_T<<<dim3(32, 8, 32), 256>>>(P,  hf + O_PT_H, hf + O_PT_L, 256, 1024);   // 4
    pack_T<<<dim3(32, 8, 32), 256>>>(Hy, hf + O_HT_H, hf + O_HT_L, 256, 1024);   // 5

    // E[b] = Fp[b] @ Fh[b]^T
    mm<0><<<dim3(4, 2, 32), 256, SM>>>(
        hf + O_FP_H, hf + O_FP_L, 1024, 262144, hf + O_FH_H, hf + O_FH_L, 1024, 262144,
        E, 256, 65536, nullptr, nullptr, 0, 0, 1024);

    softmax_pack<<<1024, dim3(32, 8)>>>(E, hf + O_AT_H, hf + O_AT_L, hf + O_TT_H, hf + O_TT_L);

    // betas = attn @ H (B = H^T, ldb=256) ; alphas = attn^T @ P (B = P^T, ldb=256)
    mm<1><<<dim3(16, 2, 32), 256, SM>>>(
        hf + O_AT_H, hf + O_AT_L, 256, 65536, hf + O_HT_H, hf + O_HT_L, 256, 262144,
        nullptr, 0, 0, hf + O_BE_H, hf + O_BE_L, 1024, 262144, 256);
    mm<1><<<dim3(16, 2, 32), 256, SM>>>(
        hf + O_TT_H, hf + O_TT_L, 256, 65536, hf + O_PT_H, hf + O_PT_L, 256, 262144,
        nullptr, 0, 0, hf + O_AL_H, hf + O_AL_L, 1024, 262144, 256);

    // fused compare (S1: z<32, S2: z>=32)
    mm_compare<<<dim3(32, 1, 64), 256, SM>>>(
        hf + O_PH_H, hf + O_PH_L, hf + O_HH_H, hf + O_HH_L,
        hf + O_BE_H, hf + O_BE_L, hf + O_AL_H, hf + O_AL_L,
        hf + O_WG_H, hf + O_WG_L, S1, S2);

    // classifier
    mlp_layer_kernel<<<dim3(16, 4), 128>>>(S1, S2, 2048, W1, b1, a1, 2048, 4096, 1);
    mlp_layer_kernel<<<dim3(16, 4), 128>>>(a1, a1, 2048, W2, b2, a2, 2048, 2048, 1);
    final_layer_kernel<<<96, 32>>>(a2, W3, b3, out);
}

// round 16
// speedup vs baseline: 1.0312x; 1.0312x over previous
#include <cuda_runtime.h>
#include <cuda_fp16.h>
#include <math.h>
#include <stdint.h>

// ---------------------------------------------------------------------------
// Decomposable-Attention NLI forward. mma.sync fp16 hi/lo-split (3 products).
// 128x64 block tile, 256 threads (8 warps 4x2, 32x32 warp tile), 2 CTAs/SM,
// hoisted ldmatrix + cp.async addresses, 2-stage K64 ring, fused launches.
// B=32, L=256, D=1024, FF=2048.
// ---------------------------------------------------------------------------

// fp16 scratch offsets (elements)
#define O_PH_H 0L
#define O_PH_L 8388608L
#define O_HH_H 16777216L
#define O_HH_L 25165824L
#define O_FP_H 33554432L
#define O_FP_L 41943040L
#define O_FH_H 50331648L
#define O_FH_L 58720256L
#define O_PT_H 67108864L
#define O_PT_L 75497472L
#define O_HT_H 83886080L
#define O_HT_L 92274688L
#define O_BE_H 100663296L
#define O_BE_L 109051904L
#define O_AL_H 117440512L
#define O_AL_L 125829120L
#define O_WF_H 134217728L
#define O_WF_L 135266304L
#define O_WG_H 136314880L
#define O_WG_L 140509184L
#define O_AT_H 144703488L
#define O_AT_L 146800640L
#define O_TT_H 148897792L
#define O_TT_L 150994944L
#define BF_TOTAL 153092096L
#define OF_E  0L
#define OF_S1 2097152L
#define OF_S2 2162688L
#define OF_A1 2228224L
#define OF_A2 2293760L
#define F32_TOTAL 2359296L

__half __device__ __align__(1024) g_hf[BF_TOTAL];
float __device__ __align__(1024) g_f32[F32_TOTAL];

// stage layout (bytes): Ah 16K | Al 16K | Bh 8K | Bl 8K = 48KB; 2 stages
#define ST_AL 16384
#define ST_BH 32768
#define ST_BL 40960
#define ST_SZ 49152

__device__ __forceinline__ uint32_t smem_u32(const void* p) {
    uint32_t a;
    asm("{ .reg .u64 t; cvta.to.shared.u64 t, %1; cvt.u32.u64 %0, t; }" : "=r"(a) : "l"(p));
    return a;
}
__device__ __forceinline__ void split1(float v, __half& h, __half& l) {
    h = __float2half_rn(v);
    l = __float2half_rn(v - __half2float(h));
}
__device__ __forceinline__ uint32_t pk(__half a, __half b) {
    return (uint32_t)__half_as_ushort(a) | ((uint32_t)__half_as_ushort(b) << 16);
}
__device__ __forceinline__ void mma_f16(float* c, const uint32_t* a, const uint32_t* b) {
    asm volatile(
        "mma.sync.aligned.m16n8k16.row.col.f32.f16.f16.f32 "
        "{%0,%1,%2,%3},{%4,%5,%6,%7},{%8,%9},{%0,%1,%2,%3};\n"
        : "+f"(c[0]), "+f"(c[1]), "+f"(c[2]), "+f"(c[3])
        : "r"(a[0]), "r"(a[1]), "r"(a[2]), "r"(a[3]), "r"(b[0]), "r"(b[1]));
}
__device__ __forceinline__ void ldsm4(uint32_t* r, uint32_t addr) {
    asm volatile("ldmatrix.sync.aligned.m8n8.x4.shared.b16 {%0,%1,%2,%3}, [%4];"
                 : "=r"(r[0]), "=r"(r[1]), "=r"(r[2]), "=r"(r[3]) : "r"(addr));
}
__device__ __forceinline__ void cp16(uint32_t dst, const __half* src) {
    asm volatile("cp.async.cg.shared.global [%0], [%1], 16;"
                 :: "r"(dst), "l"(src) : "memory");
}

// Hoisted loader offsets: 4 A-iters (128 rows) + 2 B-iters (64 rows) per thread.
struct LdOffs {
    uint32_t sA[4], gA[4], sB[2], gB[2];
};
__device__ __forceinline__ void mk_ld(LdOffs& o, long lda, long ldb, int t) {
#pragma unroll
    for (int i = 0; i < 4; i++) {
        const int idx = t + i * 256, r = idx >> 3, c = idx & 7;
        o.sA[i] = r * 128 + ((c ^ (r & 7)) << 4);
        o.gA[i] = (uint32_t)(r * lda) + c * 8;
    }
#pragma unroll
    for (int i = 0; i < 2; i++) {
        const int idx = t + i * 256, r = idx >> 3, c = idx & 7;
        o.sB[i] = r * 128 + ((c ^ (r & 7)) << 4);
        o.gB[i] = (uint32_t)(r * ldb) + c * 8;
    }
}
__device__ __forceinline__ void issue_stage(
    uint32_t sb, const LdOffs& o,
    const __half* Azh, const __half* Azl, const __half* Bzh, const __half* Bzl, long ko)
{
#pragma unroll
    for (int i = 0; i < 4; i++) {
        cp16(sb + o.sA[i],         Azh + ko + o.gA[i]);
        cp16(sb + ST_AL + o.sA[i], Azl + ko + o.gA[i]);
    }
#pragma unroll
    for (int i = 0; i < 2; i++) {
        cp16(sb + ST_BH + o.sB[i], Bzh + ko + o.gB[i]);
        cp16(sb + ST_BL + o.sB[i], Bzl + ko + o.gB[i]);
    }
    asm volatile("cp.async.commit_group;" ::: "memory");
}

// Precompute stage-relative ldmatrix offsets for this warp (K64 stage, 4 s-steps).
__device__ __forceinline__ void mk_addrs(uint32_t aA[2][4], uint32_t aB[2][4],
                                         int wm, int wn, int lane) {
    const int lm = lane & 7, mat = lane >> 3;
    const int rsel = (mat & 1) * 8 + lm;
    const int csel = mat >> 1;
#pragma unroll
    for (int s = 0; s < 4; s++) {
        const int ch = 2 * s + csel;
#pragma unroll
        for (int mf = 0; mf < 2; mf++) {
            const int rm = wm * 32 + mf * 16 + rsel;
            aA[mf][s] = rm * 128 + ((ch ^ (rm & 7)) << 4);
        }
#pragma unroll
        for (int nfp = 0; nfp < 2; nfp++) {
            const int rn = wn * 32 + nfp * 16 + rsel;
            aB[nfp][s] = rn * 128 + ((ch ^ (rn & 7)) << 4);
        }
    }
}

// warp compute over one K64 stage, hoisted addresses, product-major order.
__device__ __forceinline__ void wcompute(uint32_t sb, const uint32_t aA[2][4],
                                         const uint32_t aB[2][4], float acc[2][4][4]) {
#pragma unroll
    for (int s = 0; s < 4; s++) {
        uint32_t bh[4][2], bl[4][2];
#pragma unroll
        for (int nfp = 0; nfp < 2; nfp++) {
            uint32_t q[4];
            ldsm4(q, sb + ST_BH + aB[nfp][s]);
            bh[nfp * 2][0] = q[0]; bh[nfp * 2 + 1][0] = q[1];
            bh[nfp * 2][1] = q[2]; bh[nfp * 2 + 1][1] = q[3];
            ldsm4(q, sb + ST_BL + aB[nfp][s]);
            bl[nfp * 2][0] = q[0]; bl[nfp * 2 + 1][0] = q[1];
            bl[nfp * 2][1] = q[2]; bl[nfp * 2 + 1][1] = q[3];
        }
        uint32_t ah[2][4], al[2][4];
#pragma unroll
        for (int mf = 0; mf < 2; mf++) {
            ldsm4(ah[mf], sb + aA[mf][s]);
            ldsm4(al[mf], sb + ST_AL + aA[mf][s]);
        }
#pragma unroll
        for (int mf = 0; mf < 2; mf++)
#pragma unroll
            for (int nf = 0; nf < 4; nf++) mma_f16(acc[mf][nf], ah[mf], bh[nf]);
#pragma unroll
        for (int mf = 0; mf < 2; mf++)
#pragma unroll
            for (int nf = 0; nf < 4; nf++) mma_f16(acc[mf][nf], ah[mf], bl[nf]);
#pragma unroll
        for (int mf = 0; mf < 2; mf++)
#pragma unroll
            for (int nf = 0; nf < 4; nf++) mma_f16(acc[mf][nf], al[mf], bh[nf]);
    }
}

// pack epilogue helper (EPI 1/2): write one warp tile as hi/lo packs
__device__ __forceinline__ void epi_pack(float acc[2][4][4], __half* Oh, __half* Ol,
                                         long ldo, long zoff, int bm, int bn,
                                         int wm, int wn, int lane, int do_tanh)
{
    const int r = lane >> 2, c2 = (lane & 3) * 2;
#pragma unroll
    for (int mf = 0; mf < 2; mf++)
#pragma unroll
        for (int nf = 0; nf < 4; nf++) {
            const int row = bm + wm * 32 + mf * 16 + r;
            const int col = bn + wn * 32 + nf * 8 + c2;
            float v0 = acc[mf][nf][0], v1 = acc[mf][nf][1];
            float v2 = acc[mf][nf][2], v3 = acc[mf][nf][3];
            if (do_tanh) { v0 = tanhf(v0); v1 = tanhf(v1); v2 = tanhf(v2); v3 = tanhf(v3); }
            __half h0, l0, h1, l1;
            split1(v0, h0, l0); split1(v1, h1, l1);
            const long o0 = zoff + (long)row * ldo + col;
            *(uint32_t*)&Oh[o0] = pk(h0, h1);
            *(uint32_t*)&Ol[o0] = pk(l0, l1);
            split1(v2, h0, l0); split1(v3, h1, l1);
            const long o1 = zoff + (long)(row + 8) * ldo + col;
            *(uint32_t*)&Oh[o1] = pk(h0, h1);
            *(uint32_t*)&Ol[o1] = pk(l0, l1);
        }
}

// ---------------------------------------------------------------------------
// D = A @ B^T. A[m][k], B[n][k] fp16 h/l row-major. Block tile 128x64,
// 256 threads (8 warps 4x2), 2-stage ring, 2 CTAs/SM.
// EPI: 0 = fp32 store; 1 = hi/lo pack store; 2 = tanh + pack store.
// ---------------------------------------------------------------------------
template <int EPI>
__global__ __launch_bounds__(256, 2) void mm(
    const __half* __restrict__ Ah, const __half* __restrict__ Al, long lda, long sA,
    const __half* __restrict__ Bh, const __half* __restrict__ Bl, long ldb, long sB,
    float* __restrict__ Cf, long ldc, long sC,
    __half* __restrict__ Oh, __half* __restrict__ Ol, long ldo, long sO, int K)
{
    extern __shared__ __align__(16) char dsm[];
    const uint32_t base = smem_u32(dsm);
    const int t = threadIdx.x, lane = t & 31, wid = t >> 5;
    const int wm = wid >> 1, wn = wid & 1;
    const int bm = blockIdx.y * 128, bn = blockIdx.x * 64, z = blockIdx.z;

    const __half* Azh = Ah + z * sA + (long)bm * lda;
    const __half* Azl = Al + z * sA + (long)bm * lda;
    const __half* Bzh = Bh + z * sB + (long)bn * ldb;
    const __half* Bzl = Bl + z * sB + (long)bn * ldb;
    const int ns = K >> 6;

    LdOffs lo;
    mk_ld(lo, lda, ldb, t);
    uint32_t aA[2][4], aB[2][4];
    mk_addrs(aA, aB, wm, wn, lane);

    float acc[2][4][4];
#pragma unroll
    for (int i = 0; i < 2; i++)
#pragma unroll
        for (int j = 0; j < 4; j++)
#pragma unroll
            for (int q = 0; q < 4; q++) acc[i][j][q] = 0.f;

    issue_stage(base, lo, Azh, Azl, Bzh, Bzl, 0);
    for (int j = 0; j < ns; j++) {
        if (j + 1 < ns) {
            issue_stage(base + ((j + 1) & 1) * ST_SZ, lo, Azh, Azl, Bzh, Bzl, (long)(j + 1) << 6);
            asm volatile("cp.async.wait_group 1;" ::: "memory");
        } else {
            asm volatile("cp.async.wait_group 0;" ::: "memory");
        }
        __syncthreads();
        wcompute(base + (j & 1) * ST_SZ, aA, aB, acc);
        __syncthreads();
    }

    if (EPI == 0) {
        const int r = lane >> 2, c2 = (lane & 3) * 2;
#pragma unroll
        for (int mf = 0; mf < 2; mf++)
#pragma unroll
            for (int nf = 0; nf < 4; nf++) {
                const int row = bm + wm * 32 + mf * 16 + r;
                const int col = bn + wn * 32 + nf * 8 + c2;
                *(float2*)&Cf[z * sC + (long)row * ldc + col] =
                    make_float2(acc[mf][nf][0], acc[mf][nf][1]);
                *(float2*)&Cf[z * sC + (long)(row + 8) * ldc + col] =
                    make_float2(acc[mf][nf][2], acc[mf][nf][3]);
            }
    } else {
        epi_pack(acc, Oh, Ol, ldo, z * sO, bm, bn, wm, wn, lane, EPI == 2);
    }
}

// ---------------------------------------------------------------------------
// Fused betas+alphas (z in [0,64)): half = z>>5 selects pointer set.
// Geometry fixed: lda=256, sA=65536, ldb=256, sB=262144, ldo=1024, sO=262144, K=256.
// ---------------------------------------------------------------------------
__global__ __launch_bounds__(256, 2) void mm_ba(
    const __half* __restrict__ A1h, const __half* __restrict__ A1l,
    const __half* __restrict__ B1h, const __half* __restrict__ B1l,
    __half* __restrict__ O1h, __half* __restrict__ O1l,
    const __half* __restrict__ A2h, const __half* __restrict__ A2l,
    const __half* __restrict__ B2h, const __half* __restrict__ B2l,
    __half* __restrict__ O2h, __half* __restrict__ O2l)
{
    extern __shared__ __align__(16) char dsm[];
    const uint32_t base = smem_u32(dsm);
    const int t = threadIdx.x, lane = t & 31, wid = t >> 5;
    const int wm = wid >> 1, wn = wid & 1;
    const int bm = blockIdx.y * 128, bn = blockIdx.x * 64;
    const int half = blockIdx.z >> 5, z = blockIdx.z & 31;

    const __half* Ah = half ? A2h : A1h;
    const __half* Al = half ? A2l : A1l;
    const __half* Bh = half ? B2h : B1h;
    const __half* Bl = half ? B2l : B1l;
    __half* Oh = half ? O2h : O1h;
    __half* Ol = half ? O2l : O1l;

    const __half* Azh = Ah + (long)z * 65536 + (long)bm * 256;
    const __half* Azl = Al + (long)z * 65536 + (long)bm * 256;
    const __half* Bzh = Bh + (long)z * 262144 + (long)bn * 256;
    const __half* Bzl = Bl + (long)z * 262144 + (long)bn * 256;

    LdOffs lo;
    mk_ld(lo, 256, 256, t);
    uint32_t aA[2][4], aB[2][4];
    mk_addrs(aA, aB, wm, wn, lane);

    float acc[2][4][4];
#pragma unroll
    for (int i = 0; i < 2; i++)
#pragma unroll
        for (int j = 0; j < 4; j++)
#pragma unroll
            for (int q = 0; q < 4; q++) acc[i][j][q] = 0.f;

    issue_stage(base, lo, Azh, Azl, Bzh, Bzl, 0);
    for (int j = 0; j < 4; j++) {
        if (j + 1 < 4) {
            issue_stage(base + ((j + 1) & 1) * ST_SZ, lo, Azh, Azl, Bzh, Bzl, (long)(j + 1) << 6);
            asm volatile("cp.async.wait_group 1;" ::: "memory");
        } else {
            asm volatile("cp.async.wait_group 0;" ::: "memory");
        }
        __syncthreads();
        wcompute(base + (j & 1) * ST_SZ, aA, aB, acc);
        __syncthreads();
    }
    epi_pack(acc, Oh, Ol, 1024, (long)z * 262144, bm, bn, wm, wn, lane, 0);
}

// ---------------------------------------------------------------------------
// Fused compare (S1+S2 in one launch, z in [0,64)):
// half = z>>5 selects (X1,X2,S); S[zz,n] = sum_p tanh(concat(X1,X2)[zz,p,:] @ W[:,n])
// ---------------------------------------------------------------------------
__global__ __launch_bounds__(256, 2) void mm_compare(
    const __half* __restrict__ P1h, const __half* __restrict__ P1l,
    const __half* __restrict__ P2h, const __half* __restrict__ P2l,
    const __half* __restrict__ Q1h, const __half* __restrict__ Q1l,
    const __half* __restrict__ Q2h, const __half* __restrict__ Q2l,
    const __half* __restrict__ Wh,  const __half* __restrict__ Wl,
    float* __restrict__ S1, float* __restrict__ S2)
{
    extern __shared__ __align__(16) char dsm[];
    __shared__ float red[4][64];
    const uint32_t base = smem_u32(dsm);
    const int t = threadIdx.x, lane = t & 31, wid = t >> 5;
    const int wm = wid >> 1, wn = wid & 1;
    const int bn = blockIdx.x * 64;
    const int half = blockIdx.z >> 5, z = blockIdx.z & 31;

    const __half* X1h = half ? P2h : P1h;
    const __half* X1l = half ? P2l : P1l;
    const __half* X2h = half ? Q2h : Q1h;
    const __half* X2l = half ? Q2l : Q1l;
    float* S = half ? S2 : S1;

    const __half* Wbh = Wh + (long)bn * 2048;
    const __half* Wbl = Wl + (long)bn * 2048;

    LdOffs lo;
    mk_ld(lo, 1024, 2048, t);
    uint32_t aA[2][4], aB[2][4];
    mk_addrs(aA, aB, wm, wn, lane);

    float csum[4][2];
#pragma unroll
    for (int nf = 0; nf < 4; nf++) { csum[nf][0] = 0.f; csum[nf][1] = 0.f; }

    for (int mt = 0; mt < 2; mt++) {
        float acc[2][4][4];
#pragma unroll
        for (int i = 0; i < 2; i++)
#pragma unroll
            for (int j = 0; j < 4; j++)
#pragma unroll
                for (int q = 0; q < 4; q++) acc[i][j][q] = 0.f;

        const long ro = (long)z * 262144 + (long)mt * 131072;
        auto issue = [&](int j) {
            const uint32_t sb = base + (j & 1) * ST_SZ;
            const long ko = (long)(j & 15) << 6;
            const __half* axh = (j < 16) ? X1h + ro + ko : X2h + ro + ko;
            const __half* axl = (j < 16) ? X1l + ro + ko : X2l + ro + ko;
            issue_stage(sb, lo, axh, axl, Wbh + ((long)j << 6), Wbl + ((long)j << 6), 0);
        };

        issue(0);
        for (int j = 0; j < 32; j++) {
            if (j + 1 < 32) {
                issue(j + 1);
                asm volatile("cp.async.wait_group 1;" ::: "memory");
            } else {
                asm volatile("cp.async.wait_group 0;" ::: "memory");
            }
            __syncthreads();
            wcompute(base + (j & 1) * ST_SZ, aA, aB, acc);
            __syncthreads();
        }
#pragma unroll
        for (int mf = 0; mf < 2; mf++)
#pragma unroll
            for (int nf = 0; nf < 4; nf++) {
                csum[nf][0] += tanhf(acc[mf][nf][0]) + tanhf(acc[mf][nf][2]);
                csum[nf][1] += tanhf(acc[mf][nf][1]) + tanhf(acc[mf][nf][3]);
            }
    }

    // reduce the 8 row-groups within the warp (lanes sharing lane&3)
#pragma unroll
    for (int off = 4; off <= 16; off <<= 1)
#pragma unroll
        for (int nf = 0; nf < 4; nf++) {
            csum[nf][0] += __shfl_xor_sync(0xffffffffu, csum[nf][0], off);
            csum[nf][1] += __shfl_xor_sync(0xffffffffu, csum[nf][1], off);
        }
    if (lane < 4) {
#pragma unroll
        for (int nf = 0; nf < 4; nf++) {
            red[wm][wn * 32 + nf * 8 + 2 * lane + 0] = csum[nf][0];
            red[wm][wn * 32 + nf * 8 + 2 * lane + 1] = csum[nf][1];
        }
    }
    __syncthreads();
    if (t < 64)
        S[(long)z * 2048 + bn + t] = red[0][t] + red[1][t] + red[2][t] + red[3][t];
}

// fp32 row-major -> elementwise fp16 hi/lo (same layout); two tensors via grid.y
__global__ __launch_bounds__(256) void pack_nat2(
    const float* __restrict__ X0, const float* __restrict__ X1,
    __half* __restrict__ H0, __half* __restrict__ L0,
    __half* __restrict__ H1, __half* __restrict__ L1, long n4)
{
    const long i = (long)blockIdx.x * 256 + threadIdx.x;
    if (i >= n4) return;
    const float* X = blockIdx.y ? X1 : X0;
    __half* H = blockIdx.y ? H1 : H0;
    __half* L = blockIdx.y ? L1 : L0;
    float4 v = ((const float4*)X)[i];
    __half h[4], l[4];
    split1(v.x, h[0], l[0]); split1(v.y, h[1], l[1]);
    split1(v.z, h[2], l[2]); split1(v.w, h[3], l[3]);
    ((uint2*)H)[i] = make_uint2(pk(h[0], h[1]), pk(h[2], h[3]));
    ((uint2*)L)[i] = make_uint2(pk(l[0], l[1]), pk(l[2], l[3]));
}

// fp32 [Z][R][C] -> fp16 hi/lo [Z][C][R]
__global__ __launch_bounds__(256) void pack_T(
    const float* __restrict__ X, __half* __restrict__ H,
    __half* __restrict__ L, int R, int C)
{
    __shared__ float tile[32][33];
    const int c0 = blockIdx.x * 32, r0 = blockIdx.y * 32;
    const int tx = threadIdx.x & 31, ty = threadIdx.x >> 5;
    const long zoff = (long)blockIdx.z * R * C;
#pragma unroll
    for (int i = 0; i < 4; i++)
        tile[ty + i * 8][tx] = X[zoff + (long)(r0 + ty + i * 8) * C + c0 + tx];
    __syncthreads();
#pragma unroll
    for (int i = 0; i < 4; i++) {
        const int c = ty + i * 8;
        __half h, l;
        split1(tile[tx][c], h, l);
        H[zoff + (long)(c0 + c) * R + r0 + tx] = h;
        L[zoff + (long)(c0 + c) * R + r0 + tx] = l;
    }
}

// softmax over 256 cols; writes attn [b][p][h] and attn^T [b][h][p] hi/lo
__global__ void softmax_pack(
    const float* __restrict__ E,
    __half* __restrict__ ATh, __half* __restrict__ ATl,
    __half* __restrict__ TTh, __half* __restrict__ TTl)
{
    __shared__ float sm[8][257];
    const int b = blockIdx.x >> 5;
    const int p0 = (blockIdx.x & 31) << 3;
    const int lane = threadIdx.x, ty = threadIdx.y;
    const float* row = E + ((long)b * 256 + p0 + ty) * 256;
    float v[8];
    float mx = -1e30f;
#pragma unroll
    for (int i = 0; i < 8; i++) { v[i] = row[i * 32 + lane]; mx = fmaxf(mx, v[i]); }
#pragma unroll
    for (int o = 16; o; o >>= 1) mx = fmaxf(mx, __shfl_xor_sync(0xffffffffu, mx, o));
    float s = 0.f;
#pragma unroll
    for (int i = 0; i < 8; i++) { v[i] = expf(v[i] - mx); s += v[i]; }
#pragma unroll
    for (int o = 16; o; o >>= 1) s += __shfl_xor_sync(0xffffffffu, s, o);
    const float inv = 1.0f / s;
#pragma unroll
    for (int i = 0; i < 8; i++) sm[ty][i * 32 + lane] = v[i] * inv;
    __syncthreads();
    const int t = ty * 32 + lane;
    {
        const int pr = t >> 5, c0 = (t & 31) << 3;
        uint32_t hw[4], lw[4];
#pragma unroll
        for (int q = 0; q < 4; q++) {
            __half h0, l0, h1, l1;
            split1(sm[pr][c0 + 2 * q], h0, l0); split1(sm[pr][c0 + 2 * q + 1], h1, l1);
            hw[q] = pk(h0, h1); lw[q] = pk(l0, l1);
        }
        const long o = ((long)b * 256 + p0 + pr) * 256 + c0;
        *(uint4*)&ATh[o] = make_uint4(hw[0], hw[1], hw[2], hw[3]);
        *(uint4*)&ATl[o] = make_uint4(lw[0], lw[1], lw[2], lw[3]);
    }
    {
        uint32_t hw[4], lw[4];
#pragma unroll
        for (int q = 0; q < 4; q++) {
            __half h0, l0, h1, l1;
            split1(sm[2 * q][t], h0, l0); split1(sm[2 * q + 1][t], h1, l1);
            hw[q] = pk(h0, h1); lw[q] = pk(l0, l1);
        }
        const long o = ((long)b * 256 + t) * 256 + p0;
        *(uint4*)&TTh[o] = make_uint4(hw[0], hw[1], hw[2], hw[3]);
        *(uint4*)&TTl[o] = make_uint4(lw[0], lw[1], lw[2], lw[3]);
    }
}

__global__ __launch_bounds__(128) void mlp_layer_kernel(
    const float* __restrict__ A1, const float* __restrict__ A2, int ksplit,
    const float* __restrict__ W, const float* __restrict__ bias,
    float* __restrict__ out, int N, int K, int do_tanh)
{
    const int n = blockIdx.x * 128 + threadIdx.x;
    const int m0 = blockIdx.y * 8;
    __shared__ float As[8][129];
    float acc[8];
#pragma unroll
    for (int i = 0; i < 8; i++) acc[i] = 0.f;
    for (int k0 = 0; k0 < K; k0 += 128) {
#pragma unroll
        for (int i = 0; i < 8; i++) {
            const int k = k0 + threadIdx.x;
            As[i][threadIdx.x] = (k < ksplit)
                ? A1[(long)(m0 + i) * ksplit + k]
                : A2[(long)(m0 + i) * ksplit + (k - ksplit)];
        }
        __syncthreads();
        for (int kk = 0; kk < 128; kk++) {
            const float wv = W[(long)(k0 + kk) * N + n];
#pragma unroll
            for (int i = 0; i < 8; i++) acc[i] += As[i][kk] * wv;
        }
        __syncthreads();
    }
    const float bb = bias[n];
#pragma unroll
    for (int i = 0; i < 8; i++) {
        float r = acc[i] + bb;
        out[(long)(m0 + i) * N + n] = do_tanh ? tanhf(r) : r;
    }
}

__global__ void final_layer_kernel(
    const float* __restrict__ A, const float* __restrict__ W3,
    const float* __restrict__ b3, float* __restrict__ out)
{
    const int m = blockIdx.x / 3, n = blockIdx.x % 3, lane = threadIdx.x;
    float s = 0.f;
    for (int k = lane; k < 2048; k += 32)
        s += A[(long)m * 2048 + k] * W3[(long)k * 3 + n];
#pragma unroll
    for (int o = 16; o; o >>= 1) s += __shfl_xor_sync(0xffffffffu, s, o);
    if (lane == 0) out[m * 3 + n] = s + b3[n];
}

extern "C" void kernel_launch(void* const* d_in, const int* in_sizes, int n_in,
                              void* d_out, int out_size)
{
    const float* P   = (const float*)d_in[0];
    const float* Hy  = (const float*)d_in[1];
    const float* W_F = (const float*)d_in[2];
    const float* W_G = (const float*)d_in[3];
    const float* W1  = (const float*)d_in[4];
    const float* b1  = (const float*)d_in[5];
    const float* W2  = (const float*)d_in[6];
    const float* b2  = (const float*)d_in[7];
    const float* W3  = (const float*)d_in[8];
    const float* b3  = (const float*)d_in[9];
    float* out = (float*)d_out;

    __half* hf = nullptr;
    float* f32 = nullptr;
    cudaGetSymbolAddress((void**)&hf, g_hf);
    cudaGetSymbolAddress((void**)&f32, g_f32);

    const int SM = 2 * ST_SZ;  // 96KB dynamic -> 2 CTAs/SM
    cudaFuncSetAttribute(mm<0>, cudaFuncAttributeMaxDynamicSharedMemorySize, SM);
    cudaFuncSetAttribute(mm<1>, cudaFuncAttributeMaxDynamicSharedMemorySize, SM);
    cudaFuncSetAttribute(mm<2>, cudaFuncAttributeMaxDynamicSharedMemorySize, SM);
    cudaFuncSetAttribute(mm_ba, cudaFuncAttributeMaxDynamicSharedMemorySize, SM);
    cudaFuncSetAttribute(mm_compare, cudaFuncAttributeMaxDynamicSharedMemorySize, SM);

    float* E  = f32 + OF_E;
    float* S1 = f32 + OF_S1;
    float* S2 = f32 + OF_S2;
    float* a1 = f32 + OF_A1;
    float* a2 = f32 + OF_A2;

    pack_nat2<<<dim3(8192, 2), 256>>>(P, Hy, hf + O_PH_H, hf + O_PH_L,
                                      hf + O_HH_H, hf + O_HH_L, 2097152);        // 0
    pack_T<<<dim3(32, 32, 1), 256>>>(W_F, hf + O_WF_H, hf + O_WF_L, 1024, 1024); // 1
    pack_T<<<dim3(64, 64, 1), 256>>>(W_G, hf + O_WG_H, hf + O_WG_L, 2048, 2048); // 2

    // fused projections: z=0 -> P, z=1 -> H (batch stride = PH->HH offset)
    mm<2><<<dim3(16, 64, 2), 256, SM>>>(                                         // 3 <- ncu
        hf + O_PH_H, hf + O_PH_L, 1024, 16777216,
        hf + O_WF_H, hf + O_WF_L, 1024, 0,
        nullptr, 0, 0, hf + O_FP_H, hf + O_FP_L, 1024, 16777216, 1024);

    pack_T<<<dim3(32, 8, 32), 256>>>(P,  hf + O_PT_H, hf + O_PT_L, 256, 1024);   // 4
    pack_T<<<dim3(32, 8, 32), 256>>>(Hy, hf + O_HT_H, hf + O_HT_L, 256, 1024);   // 5

    // E[b] = Fp[b] @ Fh[b]^T
    mm<0><<<dim3(4, 2, 32), 256, SM>>>(
        hf + O_FP_H, hf + O_FP_L, 1024, 262144, hf + O_FH_H, hf + O_FH_L, 1024, 262144,
        E, 256, 65536, nullptr, nullptr, 0, 0, 1024);

    softmax_pack<<<1024, dim3(32, 8)>>>(E, hf + O_AT_H, hf + O_AT_L, hf + O_TT_H, hf + O_TT_L);

    // fused betas (z<32: attn @ H^T) + alphas (z>=32: attn^T @ P^T)
    mm_ba<<<dim3(16, 2, 64), 256, SM>>>(
        hf + O_AT_H, hf + O_AT_L, hf + O_HT_H, hf + O_HT_L, hf + O_BE_H, hf + O_BE_L,
        hf + O_TT_H, hf + O_TT_L, hf + O_PT_H, hf + O_PT_L, hf + O_AL_H, hf + O_AL_L);

    // fused compare (S1: z<32, S2: z>=32)
    mm_compare<<<dim3(32, 1, 64), 256, SM>>>(
        hf + O_PH_H, hf + O_PH_L, hf + O_HH_H, hf + O_HH_L,
        hf + O_BE_H, hf + O_BE_L, hf + O_AL_H, hf + O_AL_L,
        hf + O_WG_H, hf + O_WG_L, S1, S2);

    // classifier
    mlp_layer_kernel<<<dim3(16, 4), 128>>>(S1, S2, 2048, W1, b1, a1, 2048, 4096, 1);
    mlp_layer_kernel<<<dim3(16, 4), 128>>>(a1, a1, 2048, W2, b2, a2, 2048, 2048, 1);
    final_layer_kernel<<<96, 32>>>(a2, W3, b3, out);
}

// round 17
// speedup vs baseline: 1.0455x; 1.0139x over previous
#include <cuda_runtime.h>
#include <cuda_fp16.h>
#include <math.h>
#include <stdint.h>

// ---------------------------------------------------------------------------
// Decomposable-Attention NLI forward. mma.sync fp16 hi/lo-split (3 products).
// 128x64 block tile, 256 threads (8 warps 4x2, 32x32 warp tile), 2 CTAs/SM,
// hoisted ldmatrix + cp.async addresses, 2-stage K64 ring, fused launches.
// NON-VOLATILE ldsm/mma asm -> ptxas may software-pipeline across s-steps.
// B=32, L=256, D=1024, FF=2048.
// ---------------------------------------------------------------------------

// fp16 scratch offsets (elements)
#define O_PH_H 0L
#define O_PH_L 8388608L
#define O_HH_H 16777216L
#define O_HH_L 25165824L
#define O_FP_H 33554432L
#define O_FP_L 41943040L
#define O_FH_H 50331648L
#define O_FH_L 58720256L
#define O_PT_H 67108864L
#define O_PT_L 75497472L
#define O_HT_H 83886080L
#define O_HT_L 92274688L
#define O_BE_H 100663296L
#define O_BE_L 109051904L
#define O_AL_H 117440512L
#define O_AL_L 125829120L
#define O_WF_H 134217728L
#define O_WF_L 135266304L
#define O_WG_H 136314880L
#define O_WG_L 140509184L
#define O_AT_H 144703488L
#define O_AT_L 146800640L
#define O_TT_H 148897792L
#define O_TT_L 150994944L
#define BF_TOTAL 153092096L
#define OF_E  0L
#define OF_S1 2097152L
#define OF_S2 2162688L
#define OF_A1 2228224L
#define OF_A2 2293760L
#define F32_TOTAL 2359296L

__half __device__ __align__(1024) g_hf[BF_TOTAL];
float __device__ __align__(1024) g_f32[F32_TOTAL];

// stage layout (bytes): Ah 16K | Al 16K | Bh 8K | Bl 8K = 48KB; 2 stages
#define ST_AL 16384
#define ST_BH 32768
#define ST_BL 40960
#define ST_SZ 49152

__device__ __forceinline__ uint32_t smem_u32(const void* p) {
    uint32_t a;
    asm("{ .reg .u64 t; cvta.to.shared.u64 t, %1; cvt.u32.u64 %0, t; }" : "=r"(a) : "l"(p));
    return a;
}
__device__ __forceinline__ void split1(float v, __half& h, __half& l) {
    h = __float2half_rn(v);
    l = __float2half_rn(v - __half2float(h));
}
__device__ __forceinline__ uint32_t pk(__half a, __half b) {
    return (uint32_t)__half_as_ushort(a) | ((uint32_t)__half_as_ushort(b) << 16);
}
// NON-volatile: pure register math; lets ptxas schedule/interleave freely.
__device__ __forceinline__ void mma_f16(float* c, const uint32_t* a, const uint32_t* b) {
    asm("mma.sync.aligned.m16n8k16.row.col.f32.f16.f16.f32 "
        "{%0,%1,%2,%3},{%4,%5,%6,%7},{%8,%9},{%0,%1,%2,%3};\n"
        : "+f"(c[0]), "+f"(c[1]), "+f"(c[2]), "+f"(c[3])
        : "r"(a[0]), "r"(a[1]), "r"(a[2]), "r"(a[3]), "r"(b[0]), "r"(b[1]));
}
// NON-volatile but with memory clobber: stays ordered vs barriers/cp.async,
// can slide across mma for software pipelining.
__device__ __forceinline__ void ldsm4(uint32_t* r, uint32_t addr) {
    asm("ldmatrix.sync.aligned.m8n8.x4.shared.b16 {%0,%1,%2,%3}, [%4];"
        : "=r"(r[0]), "=r"(r[1]), "=r"(r[2]), "=r"(r[3]) : "r"(addr) : "memory");
}
__device__ __forceinline__ void cp16(uint32_t dst, const __half* src) {
    asm volatile("cp.async.cg.shared.global [%0], [%1], 16;"
                 :: "r"(dst), "l"(src) : "memory");
}

// Hoisted loader offsets: 4 A-iters (128 rows) + 2 B-iters (64 rows) per thread.
struct LdOffs {
    uint32_t sA[4], gA[4], sB[2], gB[2];
};
__device__ __forceinline__ void mk_ld(LdOffs& o, long lda, long ldb, int t) {
#pragma unroll
    for (int i = 0; i < 4; i++) {
        const int idx = t + i * 256, r = idx >> 3, c = idx & 7;
        o.sA[i] = r * 128 + ((c ^ (r & 7)) << 4);
        o.gA[i] = (uint32_t)(r * lda) + c * 8;
    }
#pragma unroll
    for (int i = 0; i < 2; i++) {
        const int idx = t + i * 256, r = idx >> 3, c = idx & 7;
        o.sB[i] = r * 128 + ((c ^ (r & 7)) << 4);
        o.gB[i] = (uint32_t)(r * ldb) + c * 8;
    }
}
__device__ __forceinline__ void issue_stage(
    uint32_t sb, const LdOffs& o,
    const __half* Azh, const __half* Azl, const __half* Bzh, const __half* Bzl, long ko)
{
#pragma unroll
    for (int i = 0; i < 4; i++) {
        cp16(sb + o.sA[i],         Azh + ko + o.gA[i]);
        cp16(sb + ST_AL + o.sA[i], Azl + ko + o.gA[i]);
    }
#pragma unroll
    for (int i = 0; i < 2; i++) {
        cp16(sb + ST_BH + o.sB[i], Bzh + ko + o.gB[i]);
        cp16(sb + ST_BL + o.sB[i], Bzl + ko + o.gB[i]);
    }
    asm volatile("cp.async.commit_group;" ::: "memory");
}

// Precompute stage-relative ldmatrix offsets for this warp (K64 stage, 4 s-steps).
__device__ __forceinline__ void mk_addrs(uint32_t aA[2][4], uint32_t aB[2][4],
                                         int wm, int wn, int lane) {
    const int lm = lane & 7, mat = lane >> 3;
    const int rsel = (mat & 1) * 8 + lm;
    const int csel = mat >> 1;
#pragma unroll
    for (int s = 0; s < 4; s++) {
        const int ch = 2 * s + csel;
#pragma unroll
        for (int mf = 0; mf < 2; mf++) {
            const int rm = wm * 32 + mf * 16 + rsel;
            aA[mf][s] = rm * 128 + ((ch ^ (rm & 7)) << 4);
        }
#pragma unroll
        for (int nfp = 0; nfp < 2; nfp++) {
            const int rn = wn * 32 + nfp * 16 + rsel;
            aB[nfp][s] = rn * 128 + ((ch ^ (rn & 7)) << 4);
        }
    }
}

// warp compute over one K64 stage, hoisted addresses, product-major order.
__device__ __forceinline__ void wcompute(uint32_t sb, const uint32_t aA[2][4],
                                         const uint32_t aB[2][4], float acc[2][4][4]) {
#pragma unroll
    for (int s = 0; s < 4; s++) {
        uint32_t bh[4][2], bl[4][2];
#pragma unroll
        for (int nfp = 0; nfp < 2; nfp++) {
            uint32_t q[4];
            ldsm4(q, sb + ST_BH + aB[nfp][s]);
            bh[nfp * 2][0] = q[0]; bh[nfp * 2 + 1][0] = q[1];
            bh[nfp * 2][1] = q[2]; bh[nfp * 2 + 1][1] = q[3];
            ldsm4(q, sb + ST_BL + aB[nfp][s]);
            bl[nfp * 2][0] = q[0]; bl[nfp * 2 + 1][0] = q[1];
            bl[nfp * 2][1] = q[2]; bl[nfp * 2 + 1][1] = q[3];
        }
        uint32_t ah[2][4], al[2][4];
#pragma unroll
        for (int mf = 0; mf < 2; mf++) {
            ldsm4(ah[mf], sb + aA[mf][s]);
            ldsm4(al[mf], sb + ST_AL + aA[mf][s]);
        }
#pragma unroll
        for (int mf = 0; mf < 2; mf++)
#pragma unroll
            for (int nf = 0; nf < 4; nf++) mma_f16(acc[mf][nf], ah[mf], bh[nf]);
#pragma unroll
        for (int mf = 0; mf < 2; mf++)
#pragma unroll
            for (int nf = 0; nf < 4; nf++) mma_f16(acc[mf][nf], ah[mf], bl[nf]);
#pragma unroll
        for (int mf = 0; mf < 2; mf++)
#pragma unroll
            for (int nf = 0; nf < 4; nf++) mma_f16(acc[mf][nf], al[mf], bh[nf]);
    }
}

// pack epilogue helper (EPI 1/2): write one warp tile as hi/lo packs
__device__ __forceinline__ void epi_pack(float acc[2][4][4], __half* Oh, __half* Ol,
                                         long ldo, long zoff, int bm, int bn,
                                         int wm, int wn, int lane, int do_tanh)
{
    const int r = lane >> 2, c2 = (lane & 3) * 2;
#pragma unroll
    for (int mf = 0; mf < 2; mf++)
#pragma unroll
        for (int nf = 0; nf < 4; nf++) {
            const int row = bm + wm * 32 + mf * 16 + r;
            const int col = bn + wn * 32 + nf * 8 + c2;
            float v0 = acc[mf][nf][0], v1 = acc[mf][nf][1];
            float v2 = acc[mf][nf][2], v3 = acc[mf][nf][3];
            if (do_tanh) { v0 = tanhf(v0); v1 = tanhf(v1); v2 = tanhf(v2); v3 = tanhf(v3); }
            __half h0, l0, h1, l1;
            split1(v0, h0, l0); split1(v1, h1, l1);
            const long o0 = zoff + (long)row * ldo + col;
            *(uint32_t*)&Oh[o0] = pk(h0, h1);
            *(uint32_t*)&Ol[o0] = pk(l0, l1);
            split1(v2, h0, l0); split1(v3, h1, l1);
            const long o1 = zoff + (long)(row + 8) * ldo + col;
            *(uint32_t*)&Oh[o1] = pk(h0, h1);
            *(uint32_t*)&Ol[o1] = pk(l0, l1);
        }
}

// ---------------------------------------------------------------------------
// D = A @ B^T. A[m][k], B[n][k] fp16 h/l row-major. Block tile 128x64,
// 256 threads (8 warps 4x2), 2-stage ring, 2 CTAs/SM.
// EPI: 0 = fp32 store; 1 = hi/lo pack store; 2 = tanh + pack store.
// ---------------------------------------------------------------------------
template <int EPI>
__global__ __launch_bounds__(256, 2) void mm(
    const __half* __restrict__ Ah, const __half* __restrict__ Al, long lda, long sA,
    const __half* __restrict__ Bh, const __half* __restrict__ Bl, long ldb, long sB,
    float* __restrict__ Cf, long ldc, long sC,
    __half* __restrict__ Oh, __half* __restrict__ Ol, long ldo, long sO, int K)
{
    extern __shared__ __align__(16) char dsm[];
    const uint32_t base = smem_u32(dsm);
    const int t = threadIdx.x, lane = t & 31, wid = t >> 5;
    const int wm = wid >> 1, wn = wid & 1;
    const int bm = blockIdx.y * 128, bn = blockIdx.x * 64, z = blockIdx.z;

    const __half* Azh = Ah + z * sA + (long)bm * lda;
    const __half* Azl = Al + z * sA + (long)bm * lda;
    const __half* Bzh = Bh + z * sB + (long)bn * ldb;
    const __half* Bzl = Bl + z * sB + (long)bn * ldb;
    const int ns = K >> 6;

    LdOffs lo;
    mk_ld(lo, lda, ldb, t);
    uint32_t aA[2][4], aB[2][4];
    mk_addrs(aA, aB, wm, wn, lane);

    float acc[2][4][4];
#pragma unroll
    for (int i = 0; i < 2; i++)
#pragma unroll
        for (int j = 0; j < 4; j++)
#pragma unroll
            for (int q = 0; q < 4; q++) acc[i][j][q] = 0.f;

    issue_stage(base, lo, Azh, Azl, Bzh, Bzl, 0);
    for (int j = 0; j < ns; j++) {
        if (j + 1 < ns) {
            issue_stage(base + ((j + 1) & 1) * ST_SZ, lo, Azh, Azl, Bzh, Bzl, (long)(j + 1) << 6);
            asm volatile("cp.async.wait_group 1;" ::: "memory");
        } else {
            asm volatile("cp.async.wait_group 0;" ::: "memory");
        }
        __syncthreads();
        wcompute(base + (j & 1) * ST_SZ, aA, aB, acc);
        __syncthreads();
    }

    if (EPI == 0) {
        const int r = lane >> 2, c2 = (lane & 3) * 2;
#pragma unroll
        for (int mf = 0; mf < 2; mf++)
#pragma unroll
            for (int nf = 0; nf < 4; nf++) {
                const int row = bm + wm * 32 + mf * 16 + r;
                const int col = bn + wn * 32 + nf * 8 + c2;
                *(float2*)&Cf[z * sC + (long)row * ldc + col] =
                    make_float2(acc[mf][nf][0], acc[mf][nf][1]);
                *(float2*)&Cf[z * sC + (long)(row + 8) * ldc + col] =
                    make_float2(acc[mf][nf][2], acc[mf][nf][3]);
            }
    } else {
        epi_pack(acc, Oh, Ol, ldo, z * sO, bm, bn, wm, wn, lane, EPI == 2);
    }
}

// ---------------------------------------------------------------------------
// Fused betas+alphas (z in [0,64)): half = z>>5 selects pointer set.
// Geometry: lda=256, sA=65536, ldb=256, sB=262144, ldo=1024, sO=262144, K=256.
// ---------------------------------------------------------------------------
__global__ __launch_bounds__(256, 2) void mm_ba(
    const __half* __restrict__ A1h, const __half* __restrict__ A1l,
    const __half* __restrict__ B1h, const __half* __restrict__ B1l,
    __half* __restrict__ O1h, __half* __restrict__ O1l,
    const __half* __restrict__ A2h, const __half* __restrict__ A2l,
    const __half* __restrict__ B2h, const __half* __restrict__ B2l,
    __half* __restrict__ O2h, __half* __restrict__ O2l)
{
    extern __shared__ __align__(16) char dsm[];
    const uint32_t base = smem_u32(dsm);
    const int t = threadIdx.x, lane = t & 31, wid = t >> 5;
    const int wm = wid >> 1, wn = wid & 1;
    const int bm = blockIdx.y * 128, bn = blockIdx.x * 64;
    const int half = blockIdx.z >> 5, z = blockIdx.z & 31;

    const __half* Ah = half ? A2h : A1h;
    const __half* Al = half ? A2l : A1l;
    const __half* Bh = half ? B2h : B1h;
    const __half* Bl = half ? B2l : B1l;
    __half* Oh = half ? O2h : O1h;
    __half* Ol = half ? O2l : O1l;

    const __half* Azh = Ah + (long)z * 65536 + (long)bm * 256;
    const __half* Azl = Al + (long)z * 65536 + (long)bm * 256;
    const __half* Bzh = Bh + (long)z * 262144 + (long)bn * 256;
    const __half* Bzl = Bl + (long)z * 262144 + (long)bn * 256;

    LdOffs lo;
    mk_ld(lo, 256, 256, t);
    uint32_t aA[2][4], aB[2][4];
    mk_addrs(aA, aB, wm, wn, lane);

    float acc[2][4][4];
#pragma unroll
    for (int i = 0; i < 2; i++)
#pragma unroll
        for (int j = 0; j < 4; j++)
#pragma unroll
            for (int q = 0; q < 4; q++) acc[i][j][q] = 0.f;

    issue_stage(base, lo, Azh, Azl, Bzh, Bzl, 0);
    for (int j = 0; j < 4; j++) {
        if (j + 1 < 4) {
            issue_stage(base + ((j + 1) & 1) * ST_SZ, lo, Azh, Azl, Bzh, Bzl, (long)(j + 1) << 6);
            asm volatile("cp.async.wait_group 1;" ::: "memory");
        } else {
            asm volatile("cp.async.wait_group 0;" ::: "memory");
        }
        __syncthreads();
        wcompute(base + (j & 1) * ST_SZ, aA, aB, acc);
        __syncthreads();
    }
    epi_pack(acc, Oh, Ol, 1024, (long)z * 262144, bm, bn, wm, wn, lane, 0);
}

// ---------------------------------------------------------------------------
// Fused compare (S1+S2 in one launch, z in [0,64)):
// half = z>>5 selects (X1,X2,S); S[zz,n] = sum_p tanh(concat(X1,X2)[zz,p,:] @ W[:,n])
// ---------------------------------------------------------------------------
__global__ __launch_bounds__(256, 2) void mm_compare(
    const __half* __restrict__ P1h, const __half* __restrict__ P1l,
    const __half* __restrict__ P2h, const __half* __restrict__ P2l,
    const __half* __restrict__ Q1h, const __half* __restrict__ Q1l,
    const __half* __restrict__ Q2h, const __half* __restrict__ Q2l,
    const __half* __restrict__ Wh,  const __half* __restrict__ Wl,
    float* __restrict__ S1, float* __restrict__ S2)
{
    extern __shared__ __align__(16) char dsm[];
    __shared__ float red[4][64];
    const uint32_t base = smem_u32(dsm);
    const int t = threadIdx.x, lane = t & 31, wid = t >> 5;
    const int wm = wid >> 1, wn = wid & 1;
    const int bn = blockIdx.x * 64;
    const int half = blockIdx.z >> 5, z = blockIdx.z & 31;

    const __half* X1h = half ? P2h : P1h;
    const __half* X1l = half ? P2l : P1l;
    const __half* X2h = half ? Q2h : Q1h;
    const __half* X2l = half ? Q2l : Q1l;
    float* S = half ? S2 : S1;

    const __half* Wbh = Wh + (long)bn * 2048;
    const __half* Wbl = Wl + (long)bn * 2048;

    LdOffs lo;
    mk_ld(lo, 1024, 2048, t);
    uint32_t aA[2][4], aB[2][4];
    mk_addrs(aA, aB, wm, wn, lane);

    float csum[4][2];
#pragma unroll
    for (int nf = 0; nf < 4; nf++) { csum[nf][0] = 0.f; csum[nf][1] = 0.f; }

    for (int mt = 0; mt < 2; mt++) {
        float acc[2][4][4];
#pragma unroll
        for (int i = 0; i < 2; i++)
#pragma unroll
            for (int j = 0; j < 4; j++)
#pragma unroll
                for (int q = 0; q < 4; q++) acc[i][j][q] = 0.f;

        const long ro = (long)z * 262144 + (long)mt * 131072;
        auto issue = [&](int j) {
            const uint32_t sb = base + (j & 1) * ST_SZ;
            const long ko = (long)(j & 15) << 6;
            const __half* axh = (j < 16) ? X1h + ro + ko : X2h + ro + ko;
            const __half* axl = (j < 16) ? X1l + ro + ko : X2l + ro + ko;
            issue_stage(sb, lo, axh, axl, Wbh + ((long)j << 6), Wbl + ((long)j << 6), 0);
        };

        issue(0);
        for (int j = 0; j < 32; j++) {
            if (j + 1 < 32) {
                issue(j + 1);
                asm volatile("cp.async.wait_group 1;" ::: "memory");
            } else {
                asm volatile("cp.async.wait_group 0;" ::: "memory");
            }
            __syncthreads();
            wcompute(base + (j & 1) * ST_SZ, aA, aB, acc);
            __syncthreads();
        }
#pragma unroll
        for (int mf = 0; mf < 2; mf++)
#pragma unroll
            for (int nf = 0; nf < 4; nf++) {
                csum[nf][0] += tanhf(acc[mf][nf][0]) + tanhf(acc[mf][nf][2]);
                csum[nf][1] += tanhf(acc[mf][nf][1]) + tanhf(acc[mf][nf][3]);
            }
    }

    // reduce the 8 row-groups within the warp (lanes sharing lane&3)
#pragma unroll
    for (int off = 4; off <= 16; off <<= 1)
#pragma unroll
        for (int nf = 0; nf < 4; nf++) {
            csum[nf][0] += __shfl_xor_sync(0xffffffffu, csum[nf][0], off);
            csum[nf][1] += __shfl_xor_sync(0xffffffffu, csum[nf][1], off);
        }
    if (lane < 4) {
#pragma unroll
        for (int nf = 0; nf < 4; nf++) {
            red[wm][wn * 32 + nf * 8 + 2 * lane + 0] = csum[nf][0];
            red[wm][wn * 32 + nf * 8 + 2 * lane + 1] = csum[nf][1];
        }
    }
    __syncthreads();
    if (t < 64)
        S[(long)z * 2048 + bn + t] = red[0][t] + red[1][t] + red[2][t] + red[3][t];
}

// fp32 row-major -> elementwise fp16 hi/lo (same layout); two tensors via grid.y
__global__ __launch_bounds__(256) void pack_nat2(
    const float* __restrict__ X0, const float* __restrict__ X1,
    __half* __restrict__ H0, __half* __restrict__ L0,
    __half* __restrict__ H1, __half* __restrict__ L1, long n4)
{
    const long i = (long)blockIdx.x * 256 + threadIdx.x;
    if (i >= n4) return;
    const float* X = blockIdx.y ? X1 : X0;
    __half* H = blockIdx.y ? H1 : H0;
    __half* L = blockIdx.y ? L1 : L0;
    float4 v = ((const float4*)X)[i];
    __half h[4], l[4];
    split1(v.x, h[0], l[0]); split1(v.y, h[1], l[1]);
    split1(v.z, h[2], l[2]); split1(v.w, h[3], l[3]);
    ((uint2*)H)[i] = make_uint2(pk(h[0], h[1]), pk(h[2], h[3]));
    ((uint2*)L)[i] = make_uint2(pk(l[0], l[1]), pk(l[2], l[3]));
}

// fp32 [Z][R][C] -> fp16 hi/lo [Z][C][R]
__global__ __launch_bounds__(256) void pack_T(
    const float* __restrict__ X, __half* __restrict__ H,
    __half* __restrict__ L, int R, int C)
{
    __shared__ float tile[32][33];
    const int c0 = blockIdx.x * 32, r0 = blockIdx.y * 32;
    const int tx = threadIdx.x & 31, ty = threadIdx.x >> 5;
    const long zoff = (long)blockIdx.z * R * C;
#pragma unroll
    for (int i = 0; i < 4; i++)
        tile[ty + i * 8][tx] = X[zoff + (long)(r0 + ty + i * 8) * C + c0 + tx];
    __syncthreads();
#pragma unroll
    for (int i = 0; i < 4; i++) {
        const int c = ty + i * 8;
        __half h, l;
        split1(tile[tx][c], h, l);
        H[zoff + (long)(c0 + c) * R + r0 + tx] = h;
        L[zoff + (long)(c0 + c) * R + r0 + tx] = l;
    }
}

// softmax over 256 cols; writes attn [b][p][h] and attn^T [b][h][p] hi/lo
__global__ void softmax_pack(
    const float* __restrict__ E,
    __half* __restrict__ ATh, __half* __restrict__ ATl,
    __half* __restrict__ TTh, __half* __restrict__ TTl)
{
    __shared__ float sm[8][257];
    const int b = blockIdx.x >> 5;
    const int p0 = (blockIdx.x & 31) << 3;
    const int lane = threadIdx.x, ty = threadIdx.y;
    const float* row = E + ((long)b * 256 + p0 + ty) * 256;
    float v[8];
    float mx = -1e30f;
#pragma unroll
    for (int i = 0; i < 8; i++) { v[i] = row[i * 32 + lane]; mx = fmaxf(mx, v[i]); }
#pragma unroll
    for (int o = 16; o; o >>= 1) mx = fmaxf(mx, __shfl_xor_sync(0xffffffffu, mx, o));
    float s = 0.f;
#pragma unroll
    for (int i = 0; i < 8; i++) { v[i] = expf(v[i] - mx); s += v[i]; }
#pragma unroll
    for (int o = 16; o; o >>= 1) s += __shfl_xor_sync(0xffffffffu, s, o);
    const float inv = 1.0f / s;
#pragma unroll
    for (int i = 0; i < 8; i++) sm[ty][i * 32 + lane] = v[i] * inv;
    __syncthreads();
    const int t = ty * 32 + lane;
    {
        const int pr = t >> 5, c0 = (t & 31) << 3;
        uint32_t hw[4], lw[4];
#pragma unroll
        for (int q = 0; q < 4; q++) {
            __half h0, l0, h1, l1;
            split1(sm[pr][c0 + 2 * q], h0, l0); split1(sm[pr][c0 + 2 * q + 1], h1, l1);
            hw[q] = pk(h0, h1); lw[q] = pk(l0, l1);
        }
        const long o = ((long)b * 256 + p0 + pr) * 256 + c0;
        *(uint4*)&ATh[o] = make_uint4(hw[0], hw[1], hw[2], hw[3]);
        *(uint4*)&ATl[o] = make_uint4(lw[0], lw[1], lw[2], lw[3]);
    }
    {
        uint32_t hw[4], lw[4];
#pragma unroll
        for (int q = 0; q < 4; q++) {
            __half h0, l0, h1, l1;
            split1(sm[2 * q][t], h0, l0); split1(sm[2 * q + 1][t], h1, l1);
            hw[q] = pk(h0, h1); lw[q] = pk(l0, l1);
        }
        const long o = ((long)b * 256 + t) * 256 + p0;
        *(uint4*)&TTh[o] = make_uint4(hw[0], hw[1], hw[2], hw[3]);
        *(uint4*)&TTl[o] = make_uint4(lw[0], lw[1], lw[2], lw[3]);
    }
}

__global__ __launch_bounds__(128) void mlp_layer_kernel(
    const float* __restrict__ A1, const float* __restrict__ A2, int ksplit,
    const float* __restrict__ W, const float* __restrict__ bias,
    float* __restrict__ out, int N, int K, int do_tanh)
{
    const int n = blockIdx.x * 128 + threadIdx.x;
    const int m0 = blockIdx.y * 8;
    __shared__ float As[8][129];
    float acc[8];
#pragma unroll
    for (int i = 0; i < 8; i++) acc[i] = 0.f;
    for (int k0 = 0; k0 < K; k0 += 128) {
#pragma unroll
        for (int i = 0; i < 8; i++) {
            const int k = k0 + threadIdx.x;
            As[i][threadIdx.x] = (k < ksplit)
                ? A1[(long)(m0 + i) * ksplit + k]
                : A2[(long)(m0 + i) * ksplit + (k - ksplit)];
        }
        __syncthreads();
        for (int kk = 0; kk < 128; kk++) {
            const float wv = W[(long)(k0 + kk) * N + n];
#pragma unroll
            for (int i = 0; i < 8; i++) acc[i] += As[i][kk] * wv;
        }
        __syncthreads();
    }
    const float bb = bias[n];
#pragma unroll
    for (int i = 0; i < 8; i++) {
        float r = acc[i] + bb;
        out[(long)(m0 + i) * N + n] = do_tanh ? tanhf(r) : r;
    }
}

__global__ void final_layer_kernel(
    const float* __restrict__ A, const float* __restrict__ W3,
    const float* __restrict__ b3, float* __restrict__ out)
{
    const int m = blockIdx.x / 3, n = blockIdx.x % 3, lane = threadIdx.x;
    float s = 0.f;
    for (int k = lane; k < 2048; k += 32)
        s += A[(long)m * 2048 + k] * W3[(long)k * 3 + n];
#pragma unroll
    for (int o = 16; o; o >>= 1) s += __shfl_xor_sync(0xffffffffu, s, o);
    if (lane == 0) out[m * 3 + n] = s + b3[n];
}

extern "C" void kernel_launch(void* const* d_in, const int* in_sizes, int n_in,
                              void* d_out, int out_size)
{
    const float* P   = (const float*)d_in[0];
    const float* Hy  = (const float*)d_in[1];
    const float* W_F = (const float*)d_in[2];
    const float* W_G = (const float*)d_in[3];
    const float* W1  = (const float*)d_in[4];
    const float* b1  = (const float*)d_in[5];
    const float* W2  = (const float*)d_in[6];
    const float* b2  = (const float*)d_in[7];
    const float* W3  = (const float*)d_in[8];
    const float* b3  = (const float*)d_in[9];
    float* out = (float*)d_out;

    __half* hf = nullptr;
    float* f32 = nullptr;
    cudaGetSymbolAddress((void**)&hf, g_hf);
    cudaGetSymbolAddress((void**)&f32, g_f32);

    const int SM = 2 * ST_SZ;  // 96KB dynamic -> 2 CTAs/SM
    cudaFuncSetAttribute(mm<0>, cudaFuncAttributeMaxDynamicSharedMemorySize, SM);
    cudaFuncSetAttribute(mm<1>, cudaFuncAttributeMaxDynamicSharedMemorySize, SM);
    cudaFuncSetAttribute(mm<2>, cudaFuncAttributeMaxDynamicSharedMemorySize, SM);
    cudaFuncSetAttribute(mm_ba, cudaFuncAttributeMaxDynamicSharedMemorySize, SM);
    cudaFuncSetAttribute(mm_compare, cudaFuncAttributeMaxDynamicSharedMemorySize, SM);

    float* E  = f32 + OF_E;
    float* S1 = f32 + OF_S1;
    float* S2 = f32 + OF_S2;
    float* a1 = f32 + OF_A1;
    float* a2 = f32 + OF_A2;

    pack_nat2<<<dim3(8192, 2), 256>>>(P, Hy, hf + O_PH_H, hf + O_PH_L,
                                      hf + O_HH_H, hf + O_HH_L, 2097152);        // 0
    pack_T<<<dim3(32, 32, 1), 256>>>(W_F, hf + O_WF_H, hf + O_WF_L, 1024, 1024); // 1
    pack_T<<<dim3(64, 64, 1), 256>>>(W_G, hf + O_WG_H, hf + O_WG_L, 2048, 2048); // 2

    // fused projections: z=0 -> P, z=1 -> H (batch stride = PH->HH offset)
    mm<2><<<dim3(16, 64, 2), 256, SM>>>(                                         // 3 <- ncu
        hf + O_PH_H, hf + O_PH_L, 1024, 16777216,
        hf + O_WF_H, hf + O_WF_L, 1024, 0,
        nullptr, 0, 0, hf + O_FP_H, hf + O_FP_L, 1024, 16777216, 1024);

    pack_T<<<dim3(32, 8, 32), 256>>>(P,  hf + O_PT_H, hf + O_PT_L, 256, 1024);   // 4
    pack_T<<<dim3(32, 8, 32), 256>>>(Hy, hf + O_HT_H, hf + O_HT_L, 256, 1024);   // 5

    // E[b] = Fp[b] @ Fh[b]^T
    mm<0><<<dim3(4, 2, 32), 256, SM>>>(
        hf + O_FP_H, hf + O_FP_L, 1024, 262144, hf + O_FH_H, hf + O_FH_L, 1024, 262144,
        E, 256, 65536, nullptr, nullptr, 0, 0, 1024);

    softmax_pack<<<1024, dim3(32, 8)>>>(E, hf + O_AT_H, hf + O_AT_L, hf + O_TT_H, hf + O_TT_L);

    // fused betas (z<32: attn @ H^T) + alphas (z>=32: attn^T @ P^T)
    mm_ba<<<dim3(16, 2, 64), 256, SM>>>(
        hf + O_AT_H, hf + O_AT_L, hf + O_HT_H, hf + O_HT_L, hf + O_BE_H, hf + O_BE_L,
        hf + O_TT_H, hf + O_TT_L, hf + O_PT_H, hf + O_PT_L, hf + O_AL_H, hf + O_AL_L);

    // fused compare (S1: z<32, S2: z>=32)
    mm_compare<<<dim3(32, 1, 64), 256, SM>>>(
        hf + O_PH_H, hf + O_PH_L, hf + O_HH_H, hf + O_HH_L,
        hf + O_BE_H, hf + O_BE_L, hf + O_AL_H, hf + O_AL_L,
        hf + O_WG_H, hf + O_WG_L, S1, S2);

    // classifier
    mlp_layer_kernel<<<dim3(16, 4), 128>>>(S1, S2, 2048, W1, b1, a1, 2048, 4096, 1);
    mlp_layer_kernel<<<dim3(16, 4), 128>>>(a1, a1, 2048, W2, b2, a2, 2048, 2048, 1);
    final_layer_kernel<<<96, 32>>>(a2, W3, b3, out);
}